// round 14
// baseline (speedup 1.0000x reference)
#include <cuda_runtime.h>
#include <cuda_bf16.h>
#include <cuda_fp16.h>
#include <cstdint>
#include <math.h>

// ---------------------------------------------------------------------------
// Problem constants
// ---------------------------------------------------------------------------
#define BATCH   2048
#define NTOK    49
#define DIM     256
#define HEADS   8
#define HDIM    32
#define NW      64
#define M_ROWS  (BATCH * NTOK)   // 100352
#define KTOT    256

// ---------------------------------------------------------------------------
// Scratch (__device__ globals: allocation-free rule)
// ---------------------------------------------------------------------------
__device__ __half  g_qkv_h[(size_t)M_ROWS * 3 * DIM];  // qkv fp16 hi [M,768]
__device__ __half  g_qkv_l[(size_t)M_ROWS * 3 * DIM];  // qkv fp16 lo
__device__ __half  g_x_h[(size_t)M_ROWS * DIM];        // x fp16 hi
__device__ __half  g_x_l[(size_t)M_ROWS * DIM];        // x fp16 lo
__device__ __half  g_att_h[(size_t)M_ROWS * DIM];      // O fp16 hi
__device__ __half  g_att_l[(size_t)M_ROWS * DIM];      // O fp16 lo
__device__ __half  g_wqkvT[3 * DIM * DIM];             // [768,256] fp16 (N,K)
__device__ __half  g_wprojT[DIM * DIM];                // [256,256] fp16
__device__ float   g_combined[(size_t)NW * HEADS * 64 * 64];

// ---------------------------------------------------------------------------
// Helpers
// ---------------------------------------------------------------------------
__device__ __forceinline__ uint32_t smem_to_u32(const void* p) {
    uint32_t a;
    asm("{ .reg .u64 t; cvta.to.shared.u64 t, %1; cvt.u32.u64 %0, t; }" : "=r"(a) : "l"(p));
    return a;
}
__device__ __forceinline__ uint32_t pack_h2(__half a, __half b) {
    __half2 t = __halves2half2(a, b);
    return *reinterpret_cast<uint32_t*>(&t);
}
__device__ __forceinline__ uint32_t pack_h2f(float a, float b) {
    return pack_h2(__float2half(a), __float2half(b));
}
__device__ __forceinline__ void mma16816f(float* c, const uint32_t* a, const uint32_t* b) {
    asm volatile(
        "mma.sync.aligned.m16n8k16.row.col.f32.f16.f16.f32 "
        "{%0,%1,%2,%3}, {%4,%5,%6,%7}, {%8,%9}, {%0,%1,%2,%3};"
        : "+f"(c[0]), "+f"(c[1]), "+f"(c[2]), "+f"(c[3])
        : "r"(a[0]), "r"(a[1]), "r"(a[2]), "r"(a[3]), "r"(b[0]), "r"(b[1]));
}
__device__ __forceinline__ void ldsm_x4(uint32_t* r, uint32_t addr) {
    asm volatile("ldmatrix.sync.aligned.m8n8.x4.shared.b16 {%0,%1,%2,%3}, [%4];"
        : "=r"(r[0]), "=r"(r[1]), "=r"(r[2]), "=r"(r[3]) : "r"(addr));
}
__device__ __forceinline__ void ldsm_x4_t(uint32_t* r, uint32_t addr) {
    asm volatile("ldmatrix.sync.aligned.m8n8.x4.trans.shared.b16 {%0,%1,%2,%3}, [%4];"
        : "=r"(r[0]), "=r"(r[1]), "=r"(r[2]), "=r"(r[3]) : "r"(addr));
}
#define CP_ASYNC16(dst_u32, src_ptr) \
    asm volatile("cp.async.cg.shared.global [%0], [%1], 16;" :: "r"(dst_u32), "l"(src_ptr))
#define CP_COMMIT() asm volatile("cp.async.commit_group;" ::: "memory")
#define CP_WAIT_ALL() asm volatile("cp.async.wait_group 0;" ::: "memory")

// ---------------------------------------------------------------------------
// Prep kernels
// ---------------------------------------------------------------------------
__global__ void split_x(const float* __restrict__ x, __half* __restrict__ xh,
                        __half* __restrict__ xl, int n4)
{
    int i = blockIdx.x * blockDim.x + threadIdx.x;
    if (i >= n4) return;
    float4 v = ((const float4*)x)[i];
    __half hx = __float2half(v.x), hy = __float2half(v.y);
    __half hz = __float2half(v.z), hw = __float2half(v.w);
    uint2 hv = make_uint2(pack_h2(hx, hy), pack_h2(hz, hw));
    uint2 lv = make_uint2(
        pack_h2f(v.x - __half2float(hx), v.y - __half2float(hy)),
        pack_h2f(v.z - __half2float(hz), v.w - __half2float(hw)));
    ((uint2*)xh)[i] = hv;
    ((uint2*)xl)[i] = lv;
}

__global__ void convert_wT(const float* __restrict__ w, __half* __restrict__ bt,
                           int K, int N)
{
    int idx = blockIdx.x * blockDim.x + threadIdx.x;
    if (idx >= K * N) return;
    int k = idx / N, n = idx % N;
    bt[(size_t)n * K + k] = __float2half(w[idx]);
}

__global__ void build_combined(const float* __restrict__ mask,
                               const float* __restrict__ bias_table,
                               const int* __restrict__ rel_index,
                               float* __restrict__ comb)
{
    int idx = blockIdx.x * blockDim.x + threadIdx.x;
    if (idx >= NW * HEADS * 64 * 64) return;
    int c = idx & 63;
    int r = (idx >> 6) & 63;
    int h = (idx >> 12) & 7;
    int w = idx >> 15;
    float v = -1e9f;
    if (r < NTOK && c < NTOK)
        v = bias_table[rel_index[r * NTOK + c] * HEADS + h] +
            mask[((size_t)w * NTOK + r) * NTOK + c];
    comb[idx] = v;
}

// ---------------------------------------------------------------------------
// Persistent-B fp16 2-product GEMM:  C = (Ah+Al) * Bh  (B rounded fp16)
// OUTH: epilogue splits C+bias into fp16 hi/lo (for QKV); else fp32.
// Grid (NFULL/128, 98); 256 threads = 8 warps (4m x 2n), warp tile 32x64.
// ---------------------------------------------------------------------------
#define TILES   8
#define BPITCH  264
#define APITCH  72
#define OFF_A   67584                    // B tile = 128*264*2 bytes
#define ASTG    36864
#define AOFF_L  18432
#define SMEM_GEMM_BYTES 141312

template<int NFULL, bool OUTH>
__global__ void __launch_bounds__(256, 1)
gemm_persist(const __half* __restrict__ Ah, const __half* __restrict__ Al,
             const __half* __restrict__ Bt,
             const float* __restrict__ bias, float* __restrict__ Cf,
             __half* __restrict__ Ch, __half* __restrict__ Cl)
{
    extern __shared__ __half sm[];
    const uint32_t smb = smem_to_u32(sm);
    const int tid  = threadIdx.x;
    const int wid  = tid >> 5, lane = tid & 31;
    const int lq   = lane >> 2, lr = lane & 3;
    const int bn   = blockIdx.x, by = blockIdx.y;
    const int wm   = (wid & 3) * 32;
    const int wn   = (wid >> 2) * 64;
    const int lrow = lane & 7, ga = lane >> 3;

    // ---- load B tile once (single fp16) ----
    {
        const __half* src = Bt + (size_t)bn * 128 * KTOT;
#pragma unroll
        for (int i = 0; i < 16; ++i) {
            int idx = i * 256 + tid;
            int n = idx >> 5, ch = idx & 31;
            CP_ASYNC16(smb + (uint32_t)(n * BPITCH + ch * 8) * 2,
                       src + (size_t)n * KTOT + ch * 8);
        }
        CP_COMMIT();
    }

    auto loadA = [&](int f) {
        int t = f >> 2, c = f & 3;
        const uint32_t sb = smb + OFF_A + (uint32_t)(f & 1) * ASTG;
        const __half* bases[2] = {Ah, Al};
#pragma unroll
        for (int a = 0; a < 2; ++a) {
            const __half* src0 = bases[a] +
                ((size_t)(by * TILES + t) * 128) * KTOT + c * 64;
#pragma unroll
            for (int i = 0; i < 4; ++i) {
                int idx = i * 256 + tid;           // 0..1023
                int row = idx >> 3, ch = idx & 7;  // 128 rows x 8 chunks
                CP_ASYNC16(sb + (uint32_t)a * AOFF_L + (uint32_t)(row * APITCH + ch * 8) * 2,
                           src0 + (size_t)row * KTOT + ch * 8);
            }
        }
        CP_COMMIT();
    };

    loadA(0);

    const uint32_t a_off = (uint32_t)((wm + (ga & 1) * 8 + lrow) * APITCH + (ga >> 1) * 8) * 2;
    const uint32_t b_off = (uint32_t)((wn + (ga >> 1) * 8 + lrow) * BPITCH + (ga & 1) * 8) * 2;

    float acc[2][8][4];
#pragma unroll
    for (int t = 0; t < 2; ++t)
#pragma unroll
        for (int j = 0; j < 8; ++j)
#pragma unroll
            for (int e = 0; e < 4; ++e) acc[t][j][e] = 0.f;

    const int NF = TILES * 4;

    for (int f = 0; f < NF; ++f) {
        CP_WAIT_ALL();
        __syncthreads();
        if (f + 1 < NF) loadA(f + 1);

        const int c = f & 3;
        const uint32_t sA = smb + OFF_A + (uint32_t)(f & 1) * ASTG;

#pragma unroll
        for (int s16 = 0; s16 < 4; ++s16) {
            const uint32_t akof = (uint32_t)(s16 * 16) * 2;
            const uint32_t bkof = (uint32_t)(c * 64 + s16 * 16) * 2;
            uint32_t afh[2][4], afl[2][4];
#pragma unroll
            for (int t = 0; t < 2; ++t) {
                const uint32_t to = (uint32_t)(t * 16 * APITCH) * 2;
                ldsm_x4(afh[t], sA + a_off + to + akof);
                ldsm_x4(afl[t], sA + AOFF_L + a_off + to + akof);
            }
            uint32_t bh4[4][4];
#pragma unroll
            for (int p = 0; p < 4; ++p) {
                const uint32_t po = (uint32_t)(p * 16 * BPITCH) * 2;
                ldsm_x4(bh4[p], smb + b_off + po + bkof);
            }
#pragma unroll
            for (int p = 0; p < 4; ++p)
#pragma unroll
                for (int t = 0; t < 2; ++t) {
                    mma16816f(acc[t][p * 2],     afh[t], bh4[p]);
                    mma16816f(acc[t][p * 2 + 1], afh[t], bh4[p] + 2);
                }
#pragma unroll
            for (int p = 0; p < 4; ++p)
#pragma unroll
                for (int t = 0; t < 2; ++t) {
                    mma16816f(acc[t][p * 2],     afl[t], bh4[p]);
                    mma16816f(acc[t][p * 2 + 1], afl[t], bh4[p] + 2);
                }
        }

        if (c == 3) {
            const int mt = by * TILES + (f >> 2);
#pragma unroll
            for (int t = 0; t < 2; ++t) {
                int r0 = mt * 128 + wm + t * 16 + lq;
#pragma unroll
                for (int j = 0; j < 8; ++j) {
                    int col = bn * 128 + wn + j * 8 + lr * 2;
                    float b0 = bias[col], b1 = bias[col + 1];
                    float v0 = acc[t][j][0] + b0, v1 = acc[t][j][1] + b1;
                    float v2 = acc[t][j][2] + b0, v3 = acc[t][j][3] + b1;
                    if (OUTH) {
                        __half h0 = __float2half(v0), h1 = __float2half(v1);
                        __half h2 = __float2half(v2), h3 = __float2half(v3);
                        *(uint32_t*)&Ch[(size_t)r0 * NFULL + col] = pack_h2(h0, h1);
                        *(uint32_t*)&Cl[(size_t)r0 * NFULL + col] =
                            pack_h2f(v0 - __half2float(h0), v1 - __half2float(h1));
                        *(uint32_t*)&Ch[(size_t)(r0 + 8) * NFULL + col] = pack_h2(h2, h3);
                        *(uint32_t*)&Cl[(size_t)(r0 + 8) * NFULL + col] =
                            pack_h2f(v2 - __half2float(h2), v3 - __half2float(h3));
                    } else {
                        *(float2*)&Cf[(size_t)r0 * NFULL + col]       = make_float2(v0, v1);
                        *(float2*)&Cf[(size_t)(r0 + 8) * NFULL + col] = make_float2(v2, v3);
                    }
#pragma unroll
                    for (int e = 0; e < 4; ++e) acc[t][j][e] = 0.f;
                }
            }
        }
    }
}

// ---------------------------------------------------------------------------
// Tensor-core attention, fp16 direct load, fp16 3-product mma.
// One CTA per (b, h); 128 threads = 4 warps; warp w owns rows [16w,16w+16).
// Q/K/V hi/lo cp.async'd from g_qkv_h/l; V via ldmatrix.trans (k rows).
// Scale folded post-S via fmaf with combined table.
// ---------------------------------------------------------------------------
#define AP 40   // smem pitch (elems): 80B rows

__global__ void __launch_bounds__(128)
attn_mma(const __half* __restrict__ qh, const __half* __restrict__ ql,
         const float* __restrict__ comb_g,
         __half* __restrict__ att_h, __half* __restrict__ att_l)
{
    __shared__ __half sQh[64 * AP], sQl[64 * AP];
    __shared__ __half sKh[64 * AP], sKl[64 * AP];
    __shared__ __half sVh[64 * AP], sVl[64 * AP];

    const int b = blockIdx.x;
    const int h = blockIdx.y;
    const int w = b & (NW - 1);
    const int tid  = threadIdx.x;
    const int lane = tid & 31;
    const int lq   = lane >> 2, lr = lane & 3;
    const int wm   = (tid >> 5) * 16;
    const int lrow = lane & 7, ga = lane >> 3;

    const uint32_t uQh = smem_to_u32(sQh), uQl = smem_to_u32(sQl);
    const uint32_t uKh = smem_to_u32(sKh), uKl = smem_to_u32(sKl);
    const uint32_t uVh = smem_to_u32(sVh), uVl = smem_to_u32(sVl);
    const uint32_t bases[6] = {uQh, uQl, uKh, uKl, uVh, uVl};

    // zero pad rows 49..63 (u32 indices 980..1279) of each array
    for (int i = tid; i < 300; i += 128) {
        int idx = 980 + i;
        ((uint32_t*)sQh)[idx] = 0; ((uint32_t*)sQl)[idx] = 0;
        ((uint32_t*)sKh)[idx] = 0; ((uint32_t*)sKl)[idx] = 0;
        ((uint32_t*)sVh)[idx] = 0; ((uint32_t*)sVl)[idx] = 0;
    }

    // cp.async valid rows: 6 arrays x 49 rows x 4 chunks of 16B
    for (int i = tid; i < 6 * NTOK * 4; i += 128) {
        int a = i / (NTOK * 4), rem = i - a * (NTOK * 4);
        int row = rem >> 2, ch = rem & 3;
        int sect = a >> 1;   // 0=Q,1=K,2=V
        const __half* src = ((a & 1) ? ql : qh) +
            (size_t)(b * NTOK + row) * 768 + sect * 256 + h * HDIM + ch * 8;
        CP_ASYNC16(bases[a] + (uint32_t)(row * AP + ch * 8) * 2, src);
    }
    CP_COMMIT();
    CP_WAIT_ALL();
    __syncthreads();

    // frag offsets
    const uint32_t qa_off = (uint32_t)((wm + (ga & 1) * 8 + lrow) * AP + (ga >> 1) * 8) * 2;
    const uint32_t kb_off = (uint32_t)(((ga >> 1) * 8 + lrow) * AP + (ga & 1) * 8) * 2;
    const uint32_t vt_off = (uint32_t)(((ga & 1) * 8 + lrow) * AP + (ga >> 1) * 8) * 2;

    // ---- S = Q K^T (raw; product-major 3-product fp16) ----
    float c[8][4];
#pragma unroll
    for (int j = 0; j < 8; ++j)
#pragma unroll
        for (int e = 0; e < 4; ++e) c[j][e] = 0.f;

#pragma unroll
    for (int ko = 0; ko < 2; ++ko) {
        const uint32_t kof = (uint32_t)(ko * 16) * 2;
        uint32_t ah[4], al[4];
        ldsm_x4(ah, uQh + qa_off + kof);
        ldsm_x4(al, uQl + qa_off + kof);
        uint32_t bh4[4][4], bl4[4][4];
#pragma unroll
        for (int p = 0; p < 4; ++p) {
            const uint32_t po = (uint32_t)(p * 16 * AP) * 2;
            ldsm_x4(bh4[p], uKh + kb_off + po + kof);
            ldsm_x4(bl4[p], uKl + kb_off + po + kof);
        }
#pragma unroll
        for (int p = 0; p < 4; ++p) {
            mma16816f(c[p * 2],     ah, bh4[p]);
            mma16816f(c[p * 2 + 1], ah, bh4[p] + 2);
        }
#pragma unroll
        for (int p = 0; p < 4; ++p) {
            mma16816f(c[p * 2],     ah, bl4[p]);
            mma16816f(c[p * 2 + 1], ah, bl4[p] + 2);
        }
#pragma unroll
        for (int p = 0; p < 4; ++p) {
            mma16816f(c[p * 2],     al, bh4[p]);
            mma16816f(c[p * 2 + 1], al, bh4[p] + 2);
        }
    }

    // ---- scale + combined (bias+mask, padded -1e9) ----
    const float scale = 0.17677669529663687f;  // 32^-0.5
    const float* comb = comb_g + (((size_t)(w * HEADS + h) * 64) + wm + lq) * 64;
#pragma unroll
    for (int j = 0; j < 8; ++j) {
        float2 f0 = *(const float2*)(comb + j * 8 + lr * 2);
        float2 f1 = *(const float2*)(comb + 8 * 64 + j * 8 + lr * 2);
        c[j][0] = fmaf(c[j][0], scale, f0.x);
        c[j][1] = fmaf(c[j][1], scale, f0.y);
        c[j][2] = fmaf(c[j][2], scale, f1.x);
        c[j][3] = fmaf(c[j][3], scale, f1.y);
    }

    // ---- softmax ----
    float mx0 = -1e30f, mx1 = -1e30f;
#pragma unroll
    for (int j = 0; j < 8; ++j) {
        mx0 = fmaxf(mx0, fmaxf(c[j][0], c[j][1]));
        mx1 = fmaxf(mx1, fmaxf(c[j][2], c[j][3]));
    }
    mx0 = fmaxf(mx0, __shfl_xor_sync(0xffffffffu, mx0, 1));
    mx0 = fmaxf(mx0, __shfl_xor_sync(0xffffffffu, mx0, 2));
    mx1 = fmaxf(mx1, __shfl_xor_sync(0xffffffffu, mx1, 1));
    mx1 = fmaxf(mx1, __shfl_xor_sync(0xffffffffu, mx1, 2));

    float s0 = 0.f, s1 = 0.f;
#pragma unroll
    for (int j = 0; j < 8; ++j) {
        c[j][0] = __expf(c[j][0] - mx0);
        c[j][1] = __expf(c[j][1] - mx0);
        c[j][2] = __expf(c[j][2] - mx1);
        c[j][3] = __expf(c[j][3] - mx1);
        s0 += c[j][0] + c[j][1];
        s1 += c[j][2] + c[j][3];
    }
    s0 += __shfl_xor_sync(0xffffffffu, s0, 1);
    s0 += __shfl_xor_sync(0xffffffffu, s0, 2);
    s1 += __shfl_xor_sync(0xffffffffu, s1, 1);
    s1 += __shfl_xor_sync(0xffffffffu, s1, 2);
    const float inv0 = 1.0f / s0, inv1 = 1.0f / s1;
#pragma unroll
    for (int j = 0; j < 8; ++j) {
        c[j][0] *= inv0; c[j][1] *= inv0;
        c[j][2] *= inv1; c[j][3] *= inv1;
    }

    // ---- O = P V : P frags fp16 hi/lo in-register, V via ldmatrix.trans ----
    float o[4][4];
#pragma unroll
    for (int nt = 0; nt < 4; ++nt)
#pragma unroll
        for (int e = 0; e < 4; ++e) o[nt][e] = 0.f;

#pragma unroll
    for (int kk = 0; kk < 4; ++kk) {
        uint32_t ph[4], pl[4];
        const float* ca = c[2 * kk];
        const float* cb = c[2 * kk + 1];
        {
            __half h0 = __float2half(ca[0]), h1 = __float2half(ca[1]);
            __half h2 = __float2half(ca[2]), h3 = __float2half(ca[3]);
            ph[0] = pack_h2(h0, h1);
            ph[1] = pack_h2(h2, h3);
            pl[0] = pack_h2f(ca[0] - __half2float(h0), ca[1] - __half2float(h1));
            pl[1] = pack_h2f(ca[2] - __half2float(h2), ca[3] - __half2float(h3));
        }
        {
            __half h0 = __float2half(cb[0]), h1 = __float2half(cb[1]);
            __half h2 = __float2half(cb[2]), h3 = __float2half(cb[3]);
            ph[2] = pack_h2(h0, h1);
            ph[3] = pack_h2(h2, h3);
            pl[2] = pack_h2f(cb[0] - __half2float(h0), cb[1] - __half2float(h1));
            pl[3] = pack_h2f(cb[2] - __half2float(h2), cb[3] - __half2float(h3));
        }
        // V rows = tokens (k), cols = dims (n); trans x4 gives two n8 tiles
        const uint32_t rof = (uint32_t)(kk * 16 * AP) * 2;
        uint32_t vh4[2][4], vl4[2][4];
#pragma unroll
        for (int p = 0; p < 2; ++p) {
            const uint32_t co = (uint32_t)(p * 16) * 2;
            ldsm_x4_t(vh4[p], uVh + vt_off + rof + co);
            ldsm_x4_t(vl4[p], uVl + vt_off + rof + co);
        }
#pragma unroll
        for (int p = 0; p < 2; ++p) {
            mma16816f(o[p * 2],     ph, vh4[p]);
            mma16816f(o[p * 2 + 1], ph, vh4[p] + 2);
        }
#pragma unroll
        for (int p = 0; p < 2; ++p) {
            mma16816f(o[p * 2],     ph, vl4[p]);
            mma16816f(o[p * 2 + 1], ph, vl4[p] + 2);
        }
#pragma unroll
        for (int p = 0; p < 2; ++p) {
            mma16816f(o[p * 2],     pl, vh4[p]);
            mma16816f(o[p * 2 + 1], pl, vh4[p] + 2);
        }
    }

    // ---- store O as fp16 hi/lo (valid rows) ----
    int row0 = wm + lq;
    int row1 = row0 + 8;
    if (row0 < NTOK) {
        size_t eo = ((size_t)b * NTOK + row0) * DIM + h * HDIM + lr * 2;
#pragma unroll
        for (int nt = 0; nt < 4; ++nt) {
            float v0 = o[nt][0], v1 = o[nt][1];
            __half h0 = __float2half(v0), h1 = __float2half(v1);
            *(uint32_t*)(att_h + eo + nt * 8) = pack_h2(h0, h1);
            *(uint32_t*)(att_l + eo + nt * 8) =
                pack_h2f(v0 - __half2float(h0), v1 - __half2float(h1));
        }
    }
    if (row1 < NTOK) {
        size_t eo = ((size_t)b * NTOK + row1) * DIM + h * HDIM + lr * 2;
#pragma unroll
        for (int nt = 0; nt < 4; ++nt) {
            float v0 = o[nt][2], v1 = o[nt][3];
            __half h0 = __float2half(v0), h1 = __float2half(v1);
            *(uint32_t*)(att_h + eo + nt * 8) = pack_h2(h0, h1);
            *(uint32_t*)(att_l + eo + nt * 8) =
                pack_h2f(v0 - __half2float(h0), v1 - __half2float(h1));
        }
    }
}

// ---------------------------------------------------------------------------
extern "C" void kernel_launch(void* const* d_in, const int* in_sizes, int n_in,
                              void* d_out, int out_size)
{
    const float* x          = (const float*)d_in[0];
    const float* mask       = (const float*)d_in[1];
    const float* qkv_w      = (const float*)d_in[2];
    const float* qkv_b      = (const float*)d_in[3];
    const float* proj_w     = (const float*)d_in[4];
    const float* proj_b     = (const float*)d_in[5];
    const float* bias_table = (const float*)d_in[6];
    const int*   rel_index  = (const int*)d_in[7];
    float*       out        = (float*)d_out;

    void* p;
    cudaGetSymbolAddress(&p, g_qkv_h);   __half* qvh = (__half*)p;
    cudaGetSymbolAddress(&p, g_qkv_l);   __half* qvl = (__half*)p;
    cudaGetSymbolAddress(&p, g_x_h);     __half* xh  = (__half*)p;
    cudaGetSymbolAddress(&p, g_x_l);     __half* xl  = (__half*)p;
    cudaGetSymbolAddress(&p, g_att_h);   __half* ath = (__half*)p;
    cudaGetSymbolAddress(&p, g_att_l);   __half* atl = (__half*)p;
    cudaGetSymbolAddress(&p, g_wqkvT);   __half* wq  = (__half*)p;
    cudaGetSymbolAddress(&p, g_wprojT);  __half* wp  = (__half*)p;
    cudaGetSymbolAddress(&p, g_combined); float* comb = (float*)p;

    static bool attr_done = false;
    if (!attr_done) {
        cudaFuncSetAttribute(gemm_persist<3 * DIM, true>,
                             cudaFuncAttributeMaxDynamicSharedMemorySize, SMEM_GEMM_BYTES);
        cudaFuncSetAttribute(gemm_persist<DIM, false>,
                             cudaFuncAttributeMaxDynamicSharedMemorySize, SMEM_GEMM_BYTES);
        attr_done = true;
    }

    // 0) operand prep
    split_x<<<(M_ROWS * DIM / 4 + 255) / 256, 256>>>(x, xh, xl, M_ROWS * DIM / 4);
    convert_wT<<<(3 * DIM * DIM + 255) / 256, 256>>>(qkv_w, wq, DIM, 3 * DIM);
    convert_wT<<<(DIM * DIM + 255) / 256, 256>>>(proj_w, wp, DIM, DIM);
    build_combined<<<(NW * HEADS * 64 * 64) / 256, 256>>>(mask, bias_table, rel_index, comb);

    // 1) QKV projection -> fp16 hi/lo directly
    {
        dim3 grid(3 * DIM / 128, M_ROWS / 128 / TILES);   // (6, 98)
        gemm_persist<3 * DIM, true><<<grid, 256, SMEM_GEMM_BYTES>>>(
            xh, xl, wq, qkv_b, nullptr, qvh, qvl);
    }
    // 2) windowed attention (fp16 direct, 3-product)
    {
        dim3 grid(BATCH, HEADS);
        attn_mma<<<grid, 128>>>(qvh, qvl, comb, ath, atl);
    }
    // 3) output projection -> fp32 out
    {
        dim3 grid(DIM / 128, M_ROWS / 128 / TILES);       // (2, 98)
        gemm_persist<DIM, false><<<grid, 256, SMEM_GEMM_BYTES>>>(
            ath, atl, wp, proj_b, out, nullptr, nullptr);
    }
}

// round 16
// speedup vs baseline: 1.1139x; 1.1139x over previous
#include <cuda_runtime.h>
#include <cuda_bf16.h>
#include <cuda_fp16.h>
#include <cstdint>
#include <math.h>

// ---------------------------------------------------------------------------
// Problem constants
// ---------------------------------------------------------------------------
#define BATCH   2048
#define NTOK    49
#define DIM     256
#define HEADS   8
#define HDIM    32
#define NW      64
#define M_ROWS  (BATCH * NTOK)   // 100352
#define KTOT    256

// ---------------------------------------------------------------------------
// Scratch (__device__ globals: allocation-free rule)
// ---------------------------------------------------------------------------
__device__ float   g_qkv[(size_t)M_ROWS * 3 * DIM];   // fp32 [M,768]
__device__ __half  g_x_h[(size_t)M_ROWS * DIM];       // x fp16 hi
__device__ __half  g_x_l[(size_t)M_ROWS * DIM];       // x fp16 lo
__device__ __half  g_att_h[(size_t)M_ROWS * DIM];     // O fp16 hi
__device__ __half  g_att_l[(size_t)M_ROWS * DIM];     // O fp16 lo
__device__ __half  g_wqkvT[3 * DIM * DIM];            // [768,256] fp16 (N,K)
__device__ __half  g_wprojT[DIM * DIM];               // [256,256] fp16
__device__ float   g_combined[(size_t)NW * HEADS * 64 * 64];

// ---------------------------------------------------------------------------
// Helpers
// ---------------------------------------------------------------------------
__device__ __forceinline__ uint32_t smem_to_u32(const void* p) {
    uint32_t a;
    asm("{ .reg .u64 t; cvta.to.shared.u64 t, %1; cvt.u32.u64 %0, t; }" : "=r"(a) : "l"(p));
    return a;
}
__device__ __forceinline__ uint32_t pack_bf2(__nv_bfloat16 a, __nv_bfloat16 b) {
    __nv_bfloat162 t = __halves2bfloat162(a, b);
    return *reinterpret_cast<uint32_t*>(&t);
}
__device__ __forceinline__ uint32_t pack_bf2f(float a, float b) {
    return pack_bf2(__float2bfloat16(a), __float2bfloat16(b));
}
__device__ __forceinline__ uint32_t pack_h2(__half a, __half b) {
    __half2 t = __halves2half2(a, b);
    return *reinterpret_cast<uint32_t*>(&t);
}
__device__ __forceinline__ uint32_t pack_h2f(float a, float b) {
    return pack_h2(__float2half(a), __float2half(b));
}
// bf16 mma (attention)
__device__ __forceinline__ void mma16816(float* c, const uint32_t* a, const uint32_t* b) {
    asm volatile(
        "mma.sync.aligned.m16n8k16.row.col.f32.bf16.bf16.f32 "
        "{%0,%1,%2,%3}, {%4,%5,%6,%7}, {%8,%9}, {%0,%1,%2,%3};"
        : "+f"(c[0]), "+f"(c[1]), "+f"(c[2]), "+f"(c[3])
        : "r"(a[0]), "r"(a[1]), "r"(a[2]), "r"(a[3]), "r"(b[0]), "r"(b[1]));
}
// fp16 mma (GEMMs)
__device__ __forceinline__ void mma16816f(float* c, const uint32_t* a, const uint32_t* b) {
    asm volatile(
        "mma.sync.aligned.m16n8k16.row.col.f32.f16.f16.f32 "
        "{%0,%1,%2,%3}, {%4,%5,%6,%7}, {%8,%9}, {%0,%1,%2,%3};"
        : "+f"(c[0]), "+f"(c[1]), "+f"(c[2]), "+f"(c[3])
        : "r"(a[0]), "r"(a[1]), "r"(a[2]), "r"(a[3]), "r"(b[0]), "r"(b[1]));
}
__device__ __forceinline__ void ldsm_x4(uint32_t* r, uint32_t addr) {
    asm volatile("ldmatrix.sync.aligned.m8n8.x4.shared.b16 {%0,%1,%2,%3}, [%4];"
        : "=r"(r[0]), "=r"(r[1]), "=r"(r[2]), "=r"(r[3]) : "r"(addr));
}
__device__ __forceinline__ void ldsm_x4_t(uint32_t* r, uint32_t addr) {
    asm volatile("ldmatrix.sync.aligned.m8n8.x4.trans.shared.b16 {%0,%1,%2,%3}, [%4];"
        : "=r"(r[0]), "=r"(r[1]), "=r"(r[2]), "=r"(r[3]) : "r"(addr));
}
#define CP_ASYNC16(dst_u32, src_ptr) \
    asm volatile("cp.async.cg.shared.global [%0], [%1], 16;" :: "r"(dst_u32), "l"(src_ptr))
#define CP_COMMIT() asm volatile("cp.async.commit_group;" ::: "memory")
#define CP_WAIT_ALL() asm volatile("cp.async.wait_group 0;" ::: "memory")

// ---------------------------------------------------------------------------
// Prep kernels
// ---------------------------------------------------------------------------
__global__ void split_x(const float* __restrict__ x, __half* __restrict__ xh,
                        __half* __restrict__ xl, int n4)
{
    int i = blockIdx.x * blockDim.x + threadIdx.x;
    if (i >= n4) return;
    float4 v = ((const float4*)x)[i];
    __half hx = __float2half(v.x), hy = __float2half(v.y);
    __half hz = __float2half(v.z), hw = __float2half(v.w);
    uint2 hv = make_uint2(pack_h2(hx, hy), pack_h2(hz, hw));
    uint2 lv = make_uint2(
        pack_h2f(v.x - __half2float(hx), v.y - __half2float(hy)),
        pack_h2f(v.z - __half2float(hz), v.w - __half2float(hw)));
    ((uint2*)xh)[i] = hv;
    ((uint2*)xl)[i] = lv;
}

__global__ void convert_wT(const float* __restrict__ w, __half* __restrict__ bt,
                           int K, int N)
{
    int idx = blockIdx.x * blockDim.x + threadIdx.x;
    if (idx >= K * N) return;
    int k = idx / N, n = idx % N;
    bt[(size_t)n * K + k] = __float2half(w[idx]);
}

__global__ void build_combined(const float* __restrict__ mask,
                               const float* __restrict__ bias_table,
                               const int* __restrict__ rel_index,
                               float* __restrict__ comb)
{
    int idx = blockIdx.x * blockDim.x + threadIdx.x;
    if (idx >= NW * HEADS * 64 * 64) return;
    int c = idx & 63;
    int r = (idx >> 6) & 63;
    int h = (idx >> 12) & 7;
    int w = idx >> 15;
    float v = -1e9f;
    if (r < NTOK && c < NTOK)
        v = bias_table[rel_index[r * NTOK + c] * HEADS + h] +
            mask[((size_t)w * NTOK + r) * NTOK + c];
    comb[idx] = v;
}

// ---------------------------------------------------------------------------
// Persistent-B fp16 2-product GEMM:  C = (Ah+Al) * Bh
// Grid (NFULL/128, M_ROWS/128/TL); 256 threads = 8 warps (4m x 2n).
// TL = m-tiles per CTA (8 for QKV, 4 for proj to fix wave quantization).
// ---------------------------------------------------------------------------
#define BPITCH  264
#define APITCH  72
#define OFF_A   67584                    // B tile = 128*264*2 bytes
#define ASTG    36864
#define AOFF_L  18432
#define SMEM_GEMM_BYTES 141312

template<int NFULL, int TL>
__global__ void __launch_bounds__(256, 1)
gemm_persist(const __half* __restrict__ Ah, const __half* __restrict__ Al,
             const __half* __restrict__ Bt,
             const float* __restrict__ bias, float* __restrict__ Cf)
{
    extern __shared__ __half sm[];
    const uint32_t smb = smem_to_u32(sm);
    const int tid  = threadIdx.x;
    const int wid  = tid >> 5, lane = tid & 31;
    const int lq   = lane >> 2, lr = lane & 3;
    const int bn   = blockIdx.x, by = blockIdx.y;
    const int wm   = (wid & 3) * 32;
    const int wn   = (wid >> 2) * 64;
    const int lrow = lane & 7, ga = lane >> 3;

    // ---- load B tile once ----
    {
        const __half* src = Bt + (size_t)bn * 128 * KTOT;
#pragma unroll
        for (int i = 0; i < 16; ++i) {
            int idx = i * 256 + tid;
            int n = idx >> 5, ch = idx & 31;
            CP_ASYNC16(smb + (uint32_t)(n * BPITCH + ch * 8) * 2,
                       src + (size_t)n * KTOT + ch * 8);
        }
        CP_COMMIT();
    }

    auto loadA = [&](int f) {
        int t = f >> 2, c = f & 3;
        const uint32_t sb = smb + OFF_A + (uint32_t)(f & 1) * ASTG;
        const __half* bases[2] = {Ah, Al};
#pragma unroll
        for (int a = 0; a < 2; ++a) {
            const __half* src0 = bases[a] +
                ((size_t)(by * TL + t) * 128) * KTOT + c * 64;
#pragma unroll
            for (int i = 0; i < 4; ++i) {
                int idx = i * 256 + tid;           // 0..1023
                int row = idx >> 3, ch = idx & 7;  // 128 rows x 8 chunks
                CP_ASYNC16(sb + (uint32_t)a * AOFF_L + (uint32_t)(row * APITCH + ch * 8) * 2,
                           src0 + (size_t)row * KTOT + ch * 8);
            }
        }
        CP_COMMIT();
    };

    loadA(0);

    const uint32_t a_off = (uint32_t)((wm + (ga & 1) * 8 + lrow) * APITCH + (ga >> 1) * 8) * 2;
    const uint32_t b_off = (uint32_t)((wn + (ga >> 1) * 8 + lrow) * BPITCH + (ga & 1) * 8) * 2;

    float acc[2][8][4];
#pragma unroll
    for (int t = 0; t < 2; ++t)
#pragma unroll
        for (int j = 0; j < 8; ++j)
#pragma unroll
            for (int e = 0; e < 4; ++e) acc[t][j][e] = 0.f;

    const int NF = TL * 4;

    for (int f = 0; f < NF; ++f) {
        CP_WAIT_ALL();
        __syncthreads();
        if (f + 1 < NF) loadA(f + 1);

        const int c = f & 3;
        const uint32_t sA = smb + OFF_A + (uint32_t)(f & 1) * ASTG;

#pragma unroll
        for (int s16 = 0; s16 < 4; ++s16) {
            const uint32_t akof = (uint32_t)(s16 * 16) * 2;
            const uint32_t bkof = (uint32_t)(c * 64 + s16 * 16) * 2;
            uint32_t afh[2][4], afl[2][4];
#pragma unroll
            for (int t = 0; t < 2; ++t) {
                const uint32_t to = (uint32_t)(t * 16 * APITCH) * 2;
                ldsm_x4(afh[t], sA + a_off + to + akof);
                ldsm_x4(afl[t], sA + AOFF_L + a_off + to + akof);
            }
            uint32_t bh4[4][4];
#pragma unroll
            for (int p = 0; p < 4; ++p) {
                const uint32_t po = (uint32_t)(p * 16 * BPITCH) * 2;
                ldsm_x4(bh4[p], smb + b_off + po + bkof);
            }
#pragma unroll
            for (int p = 0; p < 4; ++p)
#pragma unroll
                for (int t = 0; t < 2; ++t) {
                    mma16816f(acc[t][p * 2],     afh[t], bh4[p]);
                    mma16816f(acc[t][p * 2 + 1], afh[t], bh4[p] + 2);
                }
#pragma unroll
            for (int p = 0; p < 4; ++p)
#pragma unroll
                for (int t = 0; t < 2; ++t) {
                    mma16816f(acc[t][p * 2],     afl[t], bh4[p]);
                    mma16816f(acc[t][p * 2 + 1], afl[t], bh4[p] + 2);
                }
        }

        if (c == 3) {
            const int mt = by * TL + (f >> 2);
#pragma unroll
            for (int t = 0; t < 2; ++t) {
                int r0 = mt * 128 + wm + t * 16 + lq;
#pragma unroll
                for (int j = 0; j < 8; ++j) {
                    int col = bn * 128 + wn + j * 8 + lr * 2;
                    float b0 = bias[col], b1 = bias[col + 1];
                    *(float2*)&Cf[(size_t)r0 * NFULL + col] =
                        make_float2(acc[t][j][0] + b0, acc[t][j][1] + b1);
                    *(float2*)&Cf[(size_t)(r0 + 8) * NFULL + col] =
                        make_float2(acc[t][j][2] + b0, acc[t][j][3] + b1);
#pragma unroll
                    for (int e = 0; e < 4; ++e) acc[t][j][e] = 0.f;
                }
            }
        }
    }
}

// ---------------------------------------------------------------------------
// Tensor-core attention (R13 base): fp32 qkv input, bf16 3-product,
// V token-major + ldmatrix.trans (mapping proven in R14).
// One CTA per (b, h); 128 threads.
// ---------------------------------------------------------------------------
#define AQ_LD 40   // smem pitch (elems) for Q/K/V: 80B rows

__global__ void __launch_bounds__(128)
attn_mma(const float* __restrict__ qkv, const float* __restrict__ comb_g,
         __half* __restrict__ att_h, __half* __restrict__ att_l)
{
    __shared__ __nv_bfloat16 sQh[64 * AQ_LD], sQl[64 * AQ_LD];
    __shared__ __nv_bfloat16 sKh[64 * AQ_LD], sKl[64 * AQ_LD];
    __shared__ __nv_bfloat16 sVh[64 * AQ_LD], sVl[64 * AQ_LD];

    const int b = blockIdx.x;
    const int h = blockIdx.y;
    const int w = b & (NW - 1);
    const int tid  = threadIdx.x;
    const int lane = tid & 31;
    const int lq   = lane >> 2, lr = lane & 3;
    const int wm   = (tid >> 5) * 16;
    const int lrow = lane & 7, ga = lane >> 3;

    for (int i = tid; i < 64 * AQ_LD; i += 128) {
        sQh[i] = __float2bfloat16(0.f); sQl[i] = __float2bfloat16(0.f);
        sKh[i] = __float2bfloat16(0.f); sKl[i] = __float2bfloat16(0.f);
        sVh[i] = __float2bfloat16(0.f); sVl[i] = __float2bfloat16(0.f);
    }
    __syncthreads();

    const float scale = 0.17677669529663687f;   // 32^-0.5
    const float* base = qkv + (size_t)b * NTOK * 3 * DIM + h * HDIM;
    for (int idx = tid; idx < NTOK * 8; idx += 128) {
        int n = idx >> 3, q4 = idx & 7;
        const float* rp = base + (size_t)n * 3 * DIM;
        float4 qv = *(const float4*)(rp + q4 * 4);
        qv.x *= scale; qv.y *= scale; qv.z *= scale; qv.w *= scale;
        {
            __nv_bfloat16 hx = __float2bfloat16(qv.x), hy = __float2bfloat16(qv.y);
            __nv_bfloat16 hz = __float2bfloat16(qv.z), hw = __float2bfloat16(qv.w);
            *(uint32_t*)(sQh + n * AQ_LD + q4 * 4)     = pack_bf2(hx, hy);
            *(uint32_t*)(sQh + n * AQ_LD + q4 * 4 + 2) = pack_bf2(hz, hw);
            *(uint32_t*)(sQl + n * AQ_LD + q4 * 4)     =
                pack_bf2f(qv.x - __bfloat162float(hx), qv.y - __bfloat162float(hy));
            *(uint32_t*)(sQl + n * AQ_LD + q4 * 4 + 2) =
                pack_bf2f(qv.z - __bfloat162float(hz), qv.w - __bfloat162float(hw));
        }
        float4 kv = *(const float4*)(rp + DIM + q4 * 4);
        {
            __nv_bfloat16 hx = __float2bfloat16(kv.x), hy = __float2bfloat16(kv.y);
            __nv_bfloat16 hz = __float2bfloat16(kv.z), hw = __float2bfloat16(kv.w);
            *(uint32_t*)(sKh + n * AQ_LD + q4 * 4)     = pack_bf2(hx, hy);
            *(uint32_t*)(sKh + n * AQ_LD + q4 * 4 + 2) = pack_bf2(hz, hw);
            *(uint32_t*)(sKl + n * AQ_LD + q4 * 4)     =
                pack_bf2f(kv.x - __bfloat162float(hx), kv.y - __bfloat162float(hy));
            *(uint32_t*)(sKl + n * AQ_LD + q4 * 4 + 2) =
                pack_bf2f(kv.z - __bfloat162float(hz), kv.w - __bfloat162float(hw));
        }
        float4 vv = *(const float4*)(rp + 2 * DIM + q4 * 4);
        {
            // token-major V (rows = tokens, cols = dims), vectorized stores
            __nv_bfloat16 hx = __float2bfloat16(vv.x), hy = __float2bfloat16(vv.y);
            __nv_bfloat16 hz = __float2bfloat16(vv.z), hw = __float2bfloat16(vv.w);
            *(uint32_t*)(sVh + n * AQ_LD + q4 * 4)     = pack_bf2(hx, hy);
            *(uint32_t*)(sVh + n * AQ_LD + q4 * 4 + 2) = pack_bf2(hz, hw);
            *(uint32_t*)(sVl + n * AQ_LD + q4 * 4)     =
                pack_bf2f(vv.x - __bfloat162float(hx), vv.y - __bfloat162float(hy));
            *(uint32_t*)(sVl + n * AQ_LD + q4 * 4 + 2) =
                pack_bf2f(vv.z - __bfloat162float(hz), vv.w - __bfloat162float(hw));
        }
    }
    __syncthreads();

    const uint32_t uQh = smem_to_u32(sQh), uQl = smem_to_u32(sQl);
    const uint32_t uKh = smem_to_u32(sKh), uKl = smem_to_u32(sKl);
    const uint32_t uVh = smem_to_u32(sVh), uVl = smem_to_u32(sVl);

    const uint32_t qa_off = (uint32_t)((wm + (ga & 1) * 8 + lrow) * AQ_LD + (ga >> 1) * 8) * 2;
    const uint32_t kb_off = (uint32_t)(((ga >> 1) * 8 + lrow) * AQ_LD + (ga & 1) * 8) * 2;
    const uint32_t vt_off = (uint32_t)(((ga & 1) * 8 + lrow) * AQ_LD + (ga >> 1) * 8) * 2;

    // ---- S = Qs K^T (product-major 3-product bf16) ----
    float c[8][4];
#pragma unroll
    for (int j = 0; j < 8; ++j)
#pragma unroll
        for (int e = 0; e < 4; ++e) c[j][e] = 0.f;

#pragma unroll
    for (int ko = 0; ko < 2; ++ko) {
        const uint32_t kof = (uint32_t)(ko * 16) * 2;
        uint32_t ah[4], al[4];
        ldsm_x4(ah, uQh + qa_off + kof);
        ldsm_x4(al, uQl + qa_off + kof);
        uint32_t bh4[4][4], bl4[4][4];
#pragma unroll
        for (int p = 0; p < 4; ++p) {
            const uint32_t po = (uint32_t)(p * 16 * AQ_LD) * 2;
            ldsm_x4(bh4[p], uKh + kb_off + po + kof);
            ldsm_x4(bl4[p], uKl + kb_off + po + kof);
        }
#pragma unroll
        for (int p = 0; p < 4; ++p) {
            mma16816(c[p * 2],     ah, bh4[p]);
            mma16816(c[p * 2 + 1], ah, bh4[p] + 2);
        }
#pragma unroll
        for (int p = 0; p < 4; ++p) {
            mma16816(c[p * 2],     ah, bl4[p]);
            mma16816(c[p * 2 + 1], ah, bl4[p] + 2);
        }
#pragma unroll
        for (int p = 0; p < 4; ++p) {
            mma16816(c[p * 2],     al, bh4[p]);
            mma16816(c[p * 2 + 1], al, bh4[p] + 2);
        }
    }

    // ---- + combined (bias+mask, padded -1e9) ----
    const float* comb = comb_g + (((size_t)(w * HEADS + h) * 64) + wm + lq) * 64;
#pragma unroll
    for (int j = 0; j < 8; ++j) {
        float2 f0 = *(const float2*)(comb + j * 8 + lr * 2);
        float2 f1 = *(const float2*)(comb + 8 * 64 + j * 8 + lr * 2);
        c[j][0] += f0.x; c[j][1] += f0.y;
        c[j][2] += f1.x; c[j][3] += f1.y;
    }

    // ---- softmax ----
    float mx0 = -1e30f, mx1 = -1e30f;
#pragma unroll
    for (int j = 0; j < 8; ++j) {
        mx0 = fmaxf(mx0, fmaxf(c[j][0], c[j][1]));
        mx1 = fmaxf(mx1, fmaxf(c[j][2], c[j][3]));
    }
    mx0 = fmaxf(mx0, __shfl_xor_sync(0xffffffffu, mx0, 1));
    mx0 = fmaxf(mx0, __shfl_xor_sync(0xffffffffu, mx0, 2));
    mx1 = fmaxf(mx1, __shfl_xor_sync(0xffffffffu, mx1, 1));
    mx1 = fmaxf(mx1, __shfl_xor_sync(0xffffffffu, mx1, 2));

    float s0 = 0.f, s1 = 0.f;
#pragma unroll
    for (int j = 0; j < 8; ++j) {
        c[j][0] = __expf(c[j][0] - mx0);
        c[j][1] = __expf(c[j][1] - mx0);
        c[j][2] = __expf(c[j][2] - mx1);
        c[j][3] = __expf(c[j][3] - mx1);
        s0 += c[j][0] + c[j][1];
        s1 += c[j][2] + c[j][3];
    }
    s0 += __shfl_xor_sync(0xffffffffu, s0, 1);
    s0 += __shfl_xor_sync(0xffffffffu, s0, 2);
    s1 += __shfl_xor_sync(0xffffffffu, s1, 1);
    s1 += __shfl_xor_sync(0xffffffffu, s1, 2);
    const float inv0 = 1.0f / s0, inv1 = 1.0f / s1;
#pragma unroll
    for (int j = 0; j < 8; ++j) {
        c[j][0] *= inv0; c[j][1] *= inv0;
        c[j][2] *= inv1; c[j][3] *= inv1;
    }

    // ---- O = P V : P frags in-register, V via ldmatrix.trans ----
    float o[4][4];
#pragma unroll
    for (int nt = 0; nt < 4; ++nt)
#pragma unroll
        for (int e = 0; e < 4; ++e) o[nt][e] = 0.f;

#pragma unroll
    for (int kk = 0; kk < 4; ++kk) {
        uint32_t ph[4], pl[4];
        const float* ca = c[2 * kk];
        const float* cb = c[2 * kk + 1];
        {
            __nv_bfloat16 h0 = __float2bfloat16(ca[0]), h1 = __float2bfloat16(ca[1]);
            __nv_bfloat16 h2 = __float2bfloat16(ca[2]), h3 = __float2bfloat16(ca[3]);
            ph[0] = pack_bf2(h0, h1);
            ph[1] = pack_bf2(h2, h3);
            pl[0] = pack_bf2f(ca[0] - __bfloat162float(h0), ca[1] - __bfloat162float(h1));
            pl[1] = pack_bf2f(ca[2] - __bfloat162float(h2), ca[3] - __bfloat162float(h3));
        }
        {
            __nv_bfloat16 h0 = __float2bfloat16(cb[0]), h1 = __float2bfloat16(cb[1]);
            __nv_bfloat16 h2 = __float2bfloat16(cb[2]), h3 = __float2bfloat16(cb[3]);
            ph[2] = pack_bf2(h0, h1);
            ph[3] = pack_bf2(h2, h3);
            pl[2] = pack_bf2f(cb[0] - __bfloat162float(h0), cb[1] - __bfloat162float(h1));
            pl[3] = pack_bf2f(cb[2] - __bfloat162float(h2), cb[3] - __bfloat162float(h3));
        }
        const uint32_t rof = (uint32_t)(kk * 16 * AQ_LD) * 2;
        uint32_t vh4[2][4], vl4[2][4];
#pragma unroll
        for (int p = 0; p < 2; ++p) {
            const uint32_t co = (uint32_t)(p * 16) * 2;
            ldsm_x4_t(vh4[p], uVh + vt_off + rof + co);
            ldsm_x4_t(vl4[p], uVl + vt_off + rof + co);
        }
#pragma unroll
        for (int p = 0; p < 2; ++p) {
            mma16816(o[p * 2],     ph, vh4[p]);
            mma16816(o[p * 2 + 1], ph, vh4[p] + 2);
        }
#pragma unroll
        for (int p = 0; p < 2; ++p) {
            mma16816(o[p * 2],     ph, vl4[p]);
            mma16816(o[p * 2 + 1], ph, vl4[p] + 2);
        }
#pragma unroll
        for (int p = 0; p < 2; ++p) {
            mma16816(o[p * 2],     pl, vh4[p]);
            mma16816(o[p * 2 + 1], pl, vh4[p] + 2);
        }
    }

    // ---- store O as fp16 hi/lo (valid rows) ----
    int row0 = wm + lq;
    int row1 = row0 + 8;
    if (row0 < NTOK) {
        size_t eo = ((size_t)b * NTOK + row0) * DIM + h * HDIM + lr * 2;
#pragma unroll
        for (int nt = 0; nt < 4; ++nt) {
            float v0 = o[nt][0], v1 = o[nt][1];
            __half h0 = __float2half(v0), h1 = __float2half(v1);
            *(uint32_t*)(att_h + eo + nt * 8) = pack_h2(h0, h1);
            *(uint32_t*)(att_l + eo + nt * 8) =
                pack_h2f(v0 - __half2float(h0), v1 - __half2float(h1));
        }
    }
    if (row1 < NTOK) {
        size_t eo = ((size_t)b * NTOK + row1) * DIM + h * HDIM + lr * 2;
#pragma unroll
        for (int nt = 0; nt < 4; ++nt) {
            float v0 = o[nt][2], v1 = o[nt][3];
            __half h0 = __float2half(v0), h1 = __float2half(v1);
            *(uint32_t*)(att_h + eo + nt * 8) = pack_h2(h0, h1);
            *(uint32_t*)(att_l + eo + nt * 8) =
                pack_h2f(v0 - __half2float(h0), v1 - __half2float(h1));
        }
    }
}

// ---------------------------------------------------------------------------
extern "C" void kernel_launch(void* const* d_in, const int* in_sizes, int n_in,
                              void* d_out, int out_size)
{
    const float* x          = (const float*)d_in[0];
    const float* mask       = (const float*)d_in[1];
    const float* qkv_w      = (const float*)d_in[2];
    const float* qkv_b      = (const float*)d_in[3];
    const float* proj_w     = (const float*)d_in[4];
    const float* proj_b     = (const float*)d_in[5];
    const float* bias_table = (const float*)d_in[6];
    const int*   rel_index  = (const int*)d_in[7];
    float*       out        = (float*)d_out;

    void* p;
    cudaGetSymbolAddress(&p, g_qkv);     float*  qkv_buf = (float*)p;
    cudaGetSymbolAddress(&p, g_x_h);     __half* xh  = (__half*)p;
    cudaGetSymbolAddress(&p, g_x_l);     __half* xl  = (__half*)p;
    cudaGetSymbolAddress(&p, g_att_h);   __half* ath = (__half*)p;
    cudaGetSymbolAddress(&p, g_att_l);   __half* atl = (__half*)p;
    cudaGetSymbolAddress(&p, g_wqkvT);   __half* wq  = (__half*)p;
    cudaGetSymbolAddress(&p, g_wprojT);  __half* wp  = (__half*)p;
    cudaGetSymbolAddress(&p, g_combined); float* comb = (float*)p;

    static bool attr_done = false;
    if (!attr_done) {
        cudaFuncSetAttribute(gemm_persist<3 * DIM, 8>,
                             cudaFuncAttributeMaxDynamicSharedMemorySize, SMEM_GEMM_BYTES);
        cudaFuncSetAttribute(gemm_persist<DIM, 4>,
                             cudaFuncAttributeMaxDynamicSharedMemorySize, SMEM_GEMM_BYTES);
        attr_done = true;
    }

    // 0) operand prep
    split_x<<<(M_ROWS * DIM / 4 + 255) / 256, 256>>>(x, xh, xl, M_ROWS * DIM / 4);
    convert_wT<<<(3 * DIM * DIM + 255) / 256, 256>>>(qkv_w, wq, DIM, 3 * DIM);
    convert_wT<<<(DIM * DIM + 255) / 256, 256>>>(proj_w, wp, DIM, DIM);
    build_combined<<<(NW * HEADS * 64 * 64) / 256, 256>>>(mask, bias_table, rel_index, comb);

    // 1) QKV projection (fp16 2-product persistent-B, TL=8) -> fp32
    {
        dim3 grid(3 * DIM / 128, M_ROWS / 128 / 8);   // (6, 98)
        gemm_persist<3 * DIM, 8><<<grid, 256, SMEM_GEMM_BYTES>>>(
            xh, xl, wq, qkv_b, qkv_buf);
    }
    // 2) windowed attention (bf16 3-product, trans-V)
    {
        dim3 grid(BATCH, HEADS);
        attn_mma<<<grid, 128>>>(qkv_buf, comb, ath, atl);
    }
    // 3) output projection (fp16 2-product persistent-B, TL=4) -> fp32 out
    {
        dim3 grid(DIM / 128, M_ROWS / 128 / 4);       // (2, 196)
        gemm_persist<DIM, 4><<<grid, 256, SMEM_GEMM_BYTES>>>(
            ath, atl, wp, proj_b, out);
    }
}